// round 6
// baseline (speedup 1.0000x reference)
#include <cuda_runtime.h>
#include <cuda_bf16.h>
#include <cstdint>

// Problem dims (fixed for this dataset entry)
#define BB 8
#define NN 2048
#define DD 128
#define NROWS (BB * NN)   // 16384

// ---------------- scratch (device globals; no allocation allowed) ----------
__device__ float    g_Wh  [NROWS * DD];      // tf32-rounded Wh (8 MB)
__device__ float    g_Wh1 [NROWS];
__device__ float    g_Wh2 [NROWS];
__device__ float    g_E1p [NROWS];
__device__ float    g_E1n [NROWS];
__device__ float    g_E2p [NROWS];
__device__ float    g_E2n [NROWS];
__device__ float    g_sinv[NROWS];
// ballot-permuted adjacency bitmask: word (row, it*4+e) bit L = adj[row][it*128+4L+e]
__device__ unsigned g_mask[NROWS * (NN / 32)];  // 4 MB

__device__ __forceinline__ float tf32r(float x) {
    unsigned u;
    asm("cvt.rna.tf32.f32 %0, %1;" : "=r"(u) : "f"(x));
    return __uint_as_float(u);
}

__device__ __forceinline__ void mma_tf32(float c[4], const unsigned a[4],
                                         unsigned b0, unsigned b1) {
    asm volatile(
        "mma.sync.aligned.m16n8k8.row.col.f32.tf32.tf32.f32 "
        "{%0,%1,%2,%3}, {%4,%5,%6,%7}, {%8,%9}, {%0,%1,%2,%3};\n"
        : "+f"(c[0]), "+f"(c[1]), "+f"(c[2]), "+f"(c[3])
        : "r"(a[0]), "r"(a[1]), "r"(a[2]), "r"(a[3]), "r"(b0), "r"(b1));
}

__device__ __forceinline__ uint32_t saddr(const void* p) {
    return (uint32_t)__cvta_generic_to_shared(p);
}
__device__ __forceinline__ void cp_async16(uint32_t dst, const void* src) {
    asm volatile("cp.async.cg.shared.global [%0], [%1], 16;" :: "r"(dst), "l"(src));
}

// ---------------- K1: Wh = h @ W  (fp32) + row stats + tf32 Wh store --------
// grid 256 blocks x 256 threads; each block: 64 rows x 128 cols, K=128.
__global__ __launch_bounds__(256) void k1_wh(const float* __restrict__ h,
                                             const float* __restrict__ W,
                                             const float* __restrict__ a) {
    __shared__ float sA[32][64];    // [k][m]
    __shared__ float sW[32][128];   // [k][c]
    const int tid  = threadIdx.x;
    const int m0   = blockIdx.x * 64;
    const int lane = tid & 31;
    const int r0   = (tid >> 5) << 3;   // 8 rows per warp
    const int c0   = lane << 2;         // 4 cols per lane

    float acc[8][4];
#pragma unroll
    for (int i = 0; i < 8; i++)
#pragma unroll
        for (int j = 0; j < 4; j++) acc[i][j] = 0.f;

    for (int kt = 0; kt < 128; kt += 32) {
#pragma unroll
        for (int x = tid; x < 64 * 32; x += 256) {
            int m = x >> 5, k = x & 31;
            sA[k][m] = h[(size_t)(m0 + m) * 128 + kt + k];
        }
#pragma unroll
        for (int x = tid; x < 32 * 128; x += 256) {
            int k = x >> 7, c = x & 127;
            sW[k][c] = W[(kt + k) * 128 + c];
        }
        __syncthreads();
#pragma unroll
        for (int k = 0; k < 32; k++) {
            float av[8], wv[4];
#pragma unroll
            for (int i = 0; i < 8; i++) av[i] = sA[k][r0 + i];
#pragma unroll
            for (int j = 0; j < 4; j++) wv[j] = sW[k][c0 + j];
#pragma unroll
            for (int i = 0; i < 8; i++)
#pragma unroll
                for (int j = 0; j < 4; j++) acc[i][j] = fmaf(av[i], wv[j], acc[i][j]);
        }
        __syncthreads();
    }

    // epilogue A: row stats (full fp32) via warp reduce
    float a1[4], a2[4];
#pragma unroll
    for (int j = 0; j < 4; j++) { a1[j] = a[c0 + j]; a2[j] = a[128 + c0 + j]; }
#pragma unroll
    for (int i = 0; i < 8; i++) {
        float s1 = acc[i][0] * a1[0] + acc[i][1] * a1[1] +
                   acc[i][2] * a1[2] + acc[i][3] * a1[3];
        float s2 = acc[i][0] * a2[0] + acc[i][1] * a2[1] +
                   acc[i][2] * a2[2] + acc[i][3] * a2[3];
#pragma unroll
        for (int o = 16; o; o >>= 1) {
            s1 += __shfl_xor_sync(0xffffffffu, s1, o);
            s2 += __shfl_xor_sync(0xffffffffu, s2, o);
        }
        if (lane == 0) {
            int row = m0 + r0 + i;
            g_Wh1[row] = s1;
            g_Wh2[row] = s2;
            g_E1p[row] = expf(s1);
            g_E1n[row] = expf(0.2f * s1);
            g_E2p[row] = expf(s2);
            g_E2n[row] = expf(0.2f * s2);
        }
    }
    // epilogue B: store Wh tf32-rounded (only consumer is the MMA B operand)
#pragma unroll
    for (int i = 0; i < 8; i++) {
        float4 v;
        v.x = tf32r(acc[i][0]); v.y = tf32r(acc[i][1]);
        v.z = tf32r(acc[i][2]); v.w = tf32r(acc[i][3]);
        *(float4*)(g_Wh + (size_t)(m0 + r0 + i) * 128 + c0) = v;
    }
}

// ---------------- K3: softmax denominators + permuted adj bitmask -----------
__global__ __launch_bounds__(256) void k3_denom(const int* __restrict__ adj) {
    __shared__ float sW2[NN], sP[NN], sN[NN];
    const int batch = blockIdx.y;
    const int i     = blockIdx.x * 8 + (threadIdx.x >> 5);
    const int lane  = threadIdx.x & 31;
    const int row   = batch * NN + i;

    for (int x = threadIdx.x; x < NN / 4; x += 256) {
        ((float4*)sW2)[x] = ((const float4*)(g_Wh2 + batch * NN))[x];
        ((float4*)sP)[x]  = ((const float4*)(g_E2p + batch * NN))[x];
        ((float4*)sN)[x]  = ((const float4*)(g_E2n + batch * NN))[x];
    }
    __syncthreads();

    const float w1 = g_Wh1[row];
    float accP = 0.f, accN = 0.f;
    const int4* arow = (const int4*)(adj + (size_t)row * NN);
    uint4*      mrow = (uint4*)(g_mask + (size_t)row * (NN / 32));

#pragma unroll 4
    for (int it = 0; it < 16; it++) {
        int4 av = __ldcs(arow + it * 32 + lane);
        int jb = it * 128 + lane * 4;
        float4 w2 = *(const float4*)&sW2[jb];
        float4 pp = *(const float4*)&sP[jb];
        float4 nn = *(const float4*)&sN[jb];
        unsigned b0 = __ballot_sync(0xffffffffu, av.x > 0);
        unsigned b1 = __ballot_sync(0xffffffffu, av.y > 0);
        unsigned b2 = __ballot_sync(0xffffffffu, av.z > 0);
        unsigned b3 = __ballot_sync(0xffffffffu, av.w > 0);
        if (lane == 0) mrow[it] = make_uint4(b0, b1, b2, b3);
        if (av.x > 0) { if (w1 + w2.x >= 0.f) accP += pp.x; else accN += nn.x; }
        if (av.y > 0) { if (w1 + w2.y >= 0.f) accP += pp.y; else accN += nn.y; }
        if (av.z > 0) { if (w1 + w2.z >= 0.f) accP += pp.z; else accN += nn.z; }
        if (av.w > 0) { if (w1 + w2.w >= 0.f) accP += pp.w; else accN += nn.w; }
    }
#pragma unroll
    for (int o = 16; o; o >>= 1) {
        accP += __shfl_xor_sync(0xffffffffu, accP, o);
        accN += __shfl_xor_sync(0xffffffffu, accN, o);
    }
    if (lane == 0) {
        float s = g_E1p[row] * accP + g_E1n[row] * accN;
        g_sinv[row] = (s > 0.f) ? (1.0f / s) : 0.f;
    }
}

// ---------------- K4: fused attention write + (p @ Wh) tf32 MMA, pipelined --
// grid = B * (N/64) = 256 blocks, 256 threads; 2 blocks/SM (smem ~102 KB).
// Block tile: 64 rows(i) x 128 cols(d); K loop over j in tiles of 64,
// double-buffered smem, ONE barrier per j-tile.
#define SPS 68    // sPm row stride (floats): A-frag bank = 4g+t4, conflict-free
#define SWS 136   // sWh row stride (floats): B-frag bank = 8t4+g, conflict-free
#define K4_SMEM_F (2 * 64 * SPS + 2 * 64 * SWS)
#define K4_SMEM_B (K4_SMEM_F * 4)

__global__ __launch_bounds__(256) void k4_fused(const float* __restrict__ h,
                                                float* __restrict__ outO,
                                                float* __restrict__ outA) {
    extern __shared__ float smem[];
    float* sPm = smem;                 // 2 x [64][SPS] tf32 p tile
    float* sWh = sPm + 2 * 64 * SPS;   // 2 x [64][SWS] tf32 Wh tile (cp.async)

    const int batch = blockIdx.x >> 5;
    const int i0    = (blockIdx.x & 31) << 6;
    const int tid   = threadIdx.x;
    const int warp  = tid >> 5, lane = tid & 31;
    const int g     = lane >> 2, t4 = lane & 3;
    const int wm    = warp & 1;        // M: 2 warps x 32 rows
    const int wn    = warp >> 1;       // N: 4 warps x 32 cols

    // p-loop mapping: fixed row per thread, 16 cols (cgrp) per thread
    const int pr   = tid & 63;
    const int cgrp = tid >> 6;
    const int brow = batch * NN + i0 + pr;
    const float w1   = g_Wh1[brow];
    const float inv  = g_sinv[brow];
    const float e1pI = g_E1p[brow] * inv;
    const float e1nI = g_E1n[brow] * inv;
    const uint4* maskrow = (const uint4*)(g_mask + (size_t)brow * (NN / 32));
    float* aRow = outA + (size_t)brow * NN;
    const float* WhB  = g_Wh  + (size_t)batch * NN * 128;
    const float* W2B  = g_Wh2 + batch * NN + (cgrp << 4);
    const float* EpB  = g_E2p + batch * NN + (cgrp << 4);
    const float* EnB  = g_E2n + batch * NN + (cgrp << 4);

    float acc[2][4][4];
#pragma unroll
    for (int am = 0; am < 2; am++)
#pragma unroll
        for (int bn = 0; bn < 4; bn++)
#pragma unroll
            for (int q = 0; q < 4; q++) acc[am][bn][q] = 0.f;

    auto prefetch_wh = [&](int jt, int buf) {
        const float* src = WhB + (size_t)(jt << 6) * 128;
        float* dst = sWh + buf * 64 * SWS;
#pragma unroll
        for (int x = tid; x < 64 * 32; x += 256) {
            int r = x >> 5, c4 = (x & 31) << 2;
            cp_async16(saddr(dst + r * SWS + c4), src + r * 128 + c4);
        }
        asm volatile("cp.async.commit_group;");
    };

    auto compute_p = [&](int jt, int buf) {
        const int j0 = jt << 6;
        const uint4 mw = __ldg(maskrow + (jt >> 1));
        const int halfsh = (jt & 1) << 4;
        float* dst = sPm + buf * 64 * SPS + pr * SPS + (cgrp << 4);
#pragma unroll
        for (int q = 0; q < 4; q++) {
            const int co  = q << 2;                 // within this thread's 16 cols
            const int bit = (cgrp << 2) + q + halfsh;
            float4 w2 = __ldg((const float4*)(W2B + j0 + co));
            float4 ep = __ldg((const float4*)(EpB + j0 + co));
            float4 en = __ldg((const float4*)(EnB + j0 + co));
            float p0 = ((mw.x >> bit) & 1u) ? ((w1 + w2.x >= 0.f) ? e1pI * ep.x : e1nI * en.x) : 0.f;
            float p1 = ((mw.y >> bit) & 1u) ? ((w1 + w2.y >= 0.f) ? e1pI * ep.y : e1nI * en.y) : 0.f;
            float p2 = ((mw.z >> bit) & 1u) ? ((w1 + w2.z >= 0.f) ? e1pI * ep.z : e1nI * en.z) : 0.f;
            float p3 = ((mw.w >> bit) & 1u) ? ((w1 + w2.w >= 0.f) ? e1pI * ep.w : e1nI * en.w) : 0.f;
            float4 st;
            st.x = tf32r(p0); st.y = tf32r(p1); st.z = tf32r(p2); st.w = tf32r(p3);
            *(float4*)(dst + co) = st;
            __stcs((float4*)(aRow + j0 + (cgrp << 4) + co),
                   make_float4(p0, p1, p2, p3));
        }
    };

    // ---- prologue: tile 0 ----
    prefetch_wh(0, 0);
    compute_p(0, 0);

    // ---- main loop: one barrier per j-tile ----
    for (int jt = 0; jt < 32; jt++) {
        const int cur = jt & 1, nxt = cur ^ 1;
        // barrier: (a) sPm[cur] writes from compute_p(jt) visible to all warps'
        // MMA(jt); (b) all warps' MMA(jt-1) reads of buf nxt are complete
        // before we overwrite it below.
        __syncthreads();
        if (jt < 31) {
            prefetch_wh(jt + 1, nxt);
            compute_p(jt + 1, nxt);
        }
        if (jt < 31) asm volatile("cp.async.wait_group 1;");
        else         asm volatile("cp.async.wait_group 0;");

        const float* P  = sPm + cur * 64 * SPS;
        const float* Bm = sWh + cur * 64 * SWS;
        const int rb = wm * 32;
#pragma unroll
        for (int ks = 0; ks < 8; ks++) {
            const int k0 = ks << 3;
            unsigned A0[4], A1[4];
            A0[0] = __float_as_uint(P[(rb + g)      * SPS + k0 + t4]);
            A0[1] = __float_as_uint(P[(rb + g + 8)  * SPS + k0 + t4]);
            A0[2] = __float_as_uint(P[(rb + g)      * SPS + k0 + t4 + 4]);
            A0[3] = __float_as_uint(P[(rb + g + 8)  * SPS + k0 + t4 + 4]);
            A1[0] = __float_as_uint(P[(rb + g + 16) * SPS + k0 + t4]);
            A1[1] = __float_as_uint(P[(rb + g + 24) * SPS + k0 + t4]);
            A1[2] = __float_as_uint(P[(rb + g + 16) * SPS + k0 + t4 + 4]);
            A1[3] = __float_as_uint(P[(rb + g + 24) * SPS + k0 + t4 + 4]);
#pragma unroll
            for (int bn = 0; bn < 4; bn++) {
                int col = wn * 32 + bn * 8 + g;
                unsigned b0 = __float_as_uint(Bm[(k0 + t4)     * SWS + col]);
                unsigned b1 = __float_as_uint(Bm[(k0 + t4 + 4) * SWS + col]);
                mma_tf32(acc[0][bn], A0, b0, b1);
                mma_tf32(acc[1][bn], A1, b0, b1);
            }
        }
    }

    // epilogue: out = h + h_prime
#pragma unroll
    for (int am = 0; am < 2; am++)
#pragma unroll
        for (int bn = 0; bn < 4; bn++) {
            int row = i0 + wm * 32 + am * 16 + g;
            int col = wn * 32 + bn * 8 + t4 * 2;
            size_t base  = (size_t)(batch * NN + row) * 128 + col;
            size_t base2 = base + 8 * 128;
            outO[base]      = h[base]      + acc[am][bn][0];
            outO[base + 1]  = h[base + 1]  + acc[am][bn][1];
            outO[base2]     = h[base2]     + acc[am][bn][2];
            outO[base2 + 1] = h[base2 + 1] + acc[am][bn][3];
        }
}

// ---------------- host launch ----------------------------------------------
extern "C" void kernel_launch(void* const* d_in, const int* in_sizes, int n_in,
                              void* d_out, int out_size) {
    const float* h   = (const float*)d_in[0];
    const int*   adj = (const int*)d_in[1];
    const float* W   = (const float*)d_in[2];
    const float* a   = (const float*)d_in[3];
    float* outO = (float*)d_out;
    float* outA = outO + (size_t)BB * NN * DD;

    k1_wh<<<NROWS / 64, 256>>>(h, W, a);
    k3_denom<<<dim3(NN / 8, BB), 256>>>(adj);

    cudaFuncSetAttribute(k4_fused, cudaFuncAttributeMaxDynamicSharedMemorySize,
                         K4_SMEM_B);
    k4_fused<<<BB * (NN / 64), 256, K4_SMEM_B>>>(h, outO, outA);
}

// round 10
// speedup vs baseline: 1.0992x; 1.0992x over previous
#include <cuda_runtime.h>
#include <cuda_bf16.h>
#include <cstdint>

// Problem dims (fixed for this dataset entry)
#define BB 8
#define NN 2048
#define DD 128
#define NROWS (BB * NN)   // 16384

// ---------------- scratch (device globals; no allocation allowed) ----------
__device__ float    g_Wh  [NROWS * DD];      // tf32-rounded Wh (8 MB, row-major)
__device__ float    g_Wh1 [NROWS];
__device__ float    g_Wh2 [NROWS];
__device__ float    g_E1p [NROWS];
__device__ float    g_E1n [NROWS];
__device__ float    g_E2p [NROWS];
__device__ float    g_E2n [NROWS];
__device__ float    g_sinv[NROWS];
// ballot-permuted adjacency bitmask: word (row, it*4+e) bit L = adj[row][it*128+4L+e]
__device__ unsigned g_mask[NROWS * (NN / 32)];  // 4 MB

__device__ __forceinline__ float tf32r(float x) {
    unsigned u;
    asm("cvt.rna.tf32.f32 %0, %1;" : "=r"(u) : "f"(x));
    return __uint_as_float(u);
}

__device__ __forceinline__ void mma_tf32(float c[4], const unsigned a[4],
                                         unsigned b0, unsigned b1) {
    asm volatile(
        "mma.sync.aligned.m16n8k8.row.col.f32.tf32.tf32.f32 "
        "{%0,%1,%2,%3}, {%4,%5,%6,%7}, {%8,%9}, {%0,%1,%2,%3};\n"
        : "+f"(c[0]), "+f"(c[1]), "+f"(c[2]), "+f"(c[3])
        : "r"(a[0]), "r"(a[1]), "r"(a[2]), "r"(a[3]), "r"(b0), "r"(b1));
}

__device__ __forceinline__ uint32_t saddr(const void* p) {
    return (uint32_t)__cvta_generic_to_shared(p);
}
__device__ __forceinline__ void cp_async16(uint32_t dst, const void* src) {
    asm volatile("cp.async.cg.shared.global [%0], [%1], 16;" :: "r"(dst), "l"(src));
}
__device__ __forceinline__ void bar_sync(int id, int cnt) {
    asm volatile("bar.sync %0, %1;" :: "r"(id), "r"(cnt) : "memory");
}
__device__ __forceinline__ void bar_arrive(int id, int cnt) {
    asm volatile("bar.arrive %0, %1;" :: "r"(id), "r"(cnt) : "memory");
}

// ---------------- K1: Wh = h @ W (fp32) + row stats + tf32 Wh store ---------
// grid 256 blocks x 256 threads; each block: 64 rows x 128 cols, K=128.
__global__ __launch_bounds__(256) void k1_wh(const float* __restrict__ h,
                                             const float* __restrict__ W,
                                             const float* __restrict__ a) {
    __shared__ float sA[32][64];    // [k][m]
    __shared__ float sW[32][128];   // [k][c]
    const int tid  = threadIdx.x;
    const int m0   = blockIdx.x * 64;
    const int lane = tid & 31;
    const int r0   = (tid >> 5) << 3;   // 8 rows per warp
    const int c0   = lane << 2;         // 4 cols per lane

    float acc[8][4];
#pragma unroll
    for (int i = 0; i < 8; i++)
#pragma unroll
        for (int j = 0; j < 4; j++) acc[i][j] = 0.f;

    for (int kt = 0; kt < 128; kt += 32) {
#pragma unroll
        for (int x = tid; x < 64 * 32; x += 256) {
            int m = x >> 5, k = x & 31;
            sA[k][m] = h[(size_t)(m0 + m) * 128 + kt + k];
        }
#pragma unroll
        for (int x = tid; x < 32 * 128; x += 256) {
            int k = x >> 7, c = x & 127;
            sW[k][c] = W[(kt + k) * 128 + c];
        }
        __syncthreads();
#pragma unroll
        for (int k = 0; k < 32; k++) {
            float av[8], wv[4];
#pragma unroll
            for (int i = 0; i < 8; i++) av[i] = sA[k][r0 + i];
#pragma unroll
            for (int j = 0; j < 4; j++) wv[j] = sW[k][c0 + j];
#pragma unroll
            for (int i = 0; i < 8; i++)
#pragma unroll
                for (int j = 0; j < 4; j++) acc[i][j] = fmaf(av[i], wv[j], acc[i][j]);
        }
        __syncthreads();
    }

    // epilogue A: row stats (full fp32) via warp reduce
    float a1[4], a2[4];
#pragma unroll
    for (int j = 0; j < 4; j++) { a1[j] = a[c0 + j]; a2[j] = a[128 + c0 + j]; }
#pragma unroll
    for (int i = 0; i < 8; i++) {
        float s1 = acc[i][0] * a1[0] + acc[i][1] * a1[1] +
                   acc[i][2] * a1[2] + acc[i][3] * a1[3];
        float s2 = acc[i][0] * a2[0] + acc[i][1] * a2[1] +
                   acc[i][2] * a2[2] + acc[i][3] * a2[3];
#pragma unroll
        for (int o = 16; o; o >>= 1) {
            s1 += __shfl_xor_sync(0xffffffffu, s1, o);
            s2 += __shfl_xor_sync(0xffffffffu, s2, o);
        }
        if (lane == 0) {
            int row = m0 + r0 + i;
            g_Wh1[row] = s1;
            g_Wh2[row] = s2;
            g_E1p[row] = expf(s1);
            g_E1n[row] = expf(0.2f * s1);
            g_E2p[row] = expf(s2);
            g_E2n[row] = expf(0.2f * s2);
        }
    }
    // epilogue B: store Wh tf32-rounded (only consumer is the MMA B operand)
#pragma unroll
    for (int i = 0; i < 8; i++) {
        float4 v;
        v.x = tf32r(acc[i][0]); v.y = tf32r(acc[i][1]);
        v.z = tf32r(acc[i][2]); v.w = tf32r(acc[i][3]);
        *(float4*)(g_Wh + (size_t)(m0 + r0 + i) * 128 + c0) = v;
    }
}

// ---------------- K3: softmax denominators + permuted adj bitmask -----------
__global__ __launch_bounds__(256) void k3_denom(const int* __restrict__ adj) {
    __shared__ float sW2[NN], sP[NN], sN[NN];
    const int batch = blockIdx.y;
    const int i     = blockIdx.x * 8 + (threadIdx.x >> 5);
    const int lane  = threadIdx.x & 31;
    const int row   = batch * NN + i;

    for (int x = threadIdx.x; x < NN / 4; x += 256) {
        ((float4*)sW2)[x] = ((const float4*)(g_Wh2 + batch * NN))[x];
        ((float4*)sP)[x]  = ((const float4*)(g_E2p + batch * NN))[x];
        ((float4*)sN)[x]  = ((const float4*)(g_E2n + batch * NN))[x];
    }
    __syncthreads();

    const float w1 = g_Wh1[row];
    float accP = 0.f, accN = 0.f;
    const int4* arow = (const int4*)(adj + (size_t)row * NN);
    uint4*      mrow = (uint4*)(g_mask + (size_t)row * (NN / 32));

#pragma unroll 4
    for (int it = 0; it < 16; it++) {
        int4 av = __ldcs(arow + it * 32 + lane);
        int jb = it * 128 + lane * 4;
        float4 w2 = *(const float4*)&sW2[jb];
        float4 pp = *(const float4*)&sP[jb];
        float4 nn = *(const float4*)&sN[jb];
        unsigned b0 = __ballot_sync(0xffffffffu, av.x > 0);
        unsigned b1 = __ballot_sync(0xffffffffu, av.y > 0);
        unsigned b2 = __ballot_sync(0xffffffffu, av.z > 0);
        unsigned b3 = __ballot_sync(0xffffffffu, av.w > 0);
        if (lane == 0) mrow[it] = make_uint4(b0, b1, b2, b3);
        if (av.x > 0) { if (w1 + w2.x >= 0.f) accP += pp.x; else accN += nn.x; }
        if (av.y > 0) { if (w1 + w2.y >= 0.f) accP += pp.y; else accN += nn.y; }
        if (av.z > 0) { if (w1 + w2.z >= 0.f) accP += pp.z; else accN += nn.z; }
        if (av.w > 0) { if (w1 + w2.w >= 0.f) accP += pp.w; else accN += nn.w; }
    }
#pragma unroll
    for (int o = 16; o; o >>= 1) {
        accP += __shfl_xor_sync(0xffffffffu, accP, o);
        accN += __shfl_xor_sync(0xffffffffu, accN, o);
    }
    if (lane == 0) {
        float s = g_E1p[row] * accP + g_E1n[row] * accN;
        g_sinv[row] = (s > 0.f) ? (1.0f / s) : 0.f;
    }
}

// ---------------- K4: warp-specialized producer/consumer --------------------
// grid = B * (N/128) = 128 blocks, 512 threads = 8 producer + 8 consumer warps.
// CTA tile: 128 i-rows x 128 d-cols; j-tiles of 64, double-buffered p + Wh.
// Named barriers (count 512): full[buf]=1+buf (prod arrive / cons sync),
//                             free[buf]=3+buf (cons arrive / prod sync).
#define SPS 68    // p tile row stride: A-frag bank = 4g+t4, conflict-free
#define SWS 136   // Wh tile row stride: B-frag bank = 8t4+g, conflict-free
#define SPO(buf) ((buf) * 128 * SPS)                 // float offsets
#define SBO(buf) (2 * 128 * SPS + (buf) * 64 * SWS)
#define K4_SMEM_F (2 * 128 * SPS + 2 * 64 * SWS)     // 34816 floats
#define K4_SMEM_B (K4_SMEM_F * 4)                    // 139264 bytes

__global__ __launch_bounds__(512, 1) void k4_fused(const float* __restrict__ h,
                                                   float* __restrict__ outO,
                                                   float* __restrict__ outA) {
    extern __shared__ float smem[];
    const int bat = blockIdx.x >> 4;
    const int i0  = (blockIdx.x & 15) << 7;
    const int tid = threadIdx.x;

    if (tid < 256) {
        // ===================== PRODUCERS (warps 0-7) ========================
        const int pr   = tid & 127;          // i-row within tile
        const int cgrp = tid >> 7;           // 0..1, 32 cols each
        const int brow = bat * NN + i0 + pr;
        const float w1   = g_Wh1[brow];
        const float inv  = g_sinv[brow];
        const float e1pI = g_E1p[brow] * inv;
        const float e1nI = g_E1n[brow] * inv;
        const uint4* maskrow = (const uint4*)(g_mask + (size_t)brow * (NN / 32));
        float* aRow = outA + (size_t)brow * NN;
        const float* W2B = g_Wh2 + bat * NN;
        const float* EpB = g_E2p + bat * NN;
        const float* EnB = g_E2n + bat * NN;

        for (int jt = 0; jt < 32; jt++) {
            const int buf = jt & 1;
            if (jt >= 2) bar_sync(3 + buf, 512);   // consumers released p[buf]

            const int j0 = jt << 6;
            const uint4 mw = __ldg(maskrow + (jt >> 1));
            const int halfsh = (jt & 1) << 4;
            float* dst = smem + SPO(buf) + pr * SPS;
#pragma unroll
            for (int q = 0; q < 8; q++) {
                const int cl  = (cgrp << 5) + (q << 2);     // local col 0..63
                const int bit = halfsh + (cgrp << 3) + q;
                float4 w2 = __ldg((const float4*)(W2B + j0 + cl));
                float4 ep = __ldg((const float4*)(EpB + j0 + cl));
                float4 en = __ldg((const float4*)(EnB + j0 + cl));
                float p0 = ((mw.x >> bit) & 1u) ? ((w1 + w2.x >= 0.f) ? e1pI * ep.x : e1nI * en.x) : 0.f;
                float p1 = ((mw.y >> bit) & 1u) ? ((w1 + w2.y >= 0.f) ? e1pI * ep.y : e1nI * en.y) : 0.f;
                float p2 = ((mw.z >> bit) & 1u) ? ((w1 + w2.z >= 0.f) ? e1pI * ep.z : e1nI * en.z) : 0.f;
                float p3 = ((mw.w >> bit) & 1u) ? ((w1 + w2.w >= 0.f) ? e1pI * ep.w : e1nI * en.w) : 0.f;
                float4 st;
                st.x = tf32r(p0); st.y = tf32r(p1); st.z = tf32r(p2); st.w = tf32r(p3);
                *(float4*)(dst + cl) = st;
                __stcs((float4*)(aRow + j0 + cl), make_float4(p0, p1, p2, p3));
            }
            bar_arrive(1 + buf, 512);              // p[buf] full
        }
    } else {
        // ===================== CONSUMERS (warps 8-15) =======================
        const int ct   = tid - 256;
        const int cw   = ct >> 5, lane = ct & 31;
        const int g    = lane >> 2, t4 = lane & 3;
        const int wm   = cw & 3;       // 4 warps x 32 rows
        const int wn   = cw >> 2;      // 2 warps x 64 cols
        const float* WhB = g_Wh + (size_t)bat * NN * 128;

        float acc[2][8][4];
#pragma unroll
        for (int am = 0; am < 2; am++)
#pragma unroll
            for (int bn = 0; bn < 8; bn++)
#pragma unroll
                for (int q = 0; q < 4; q++) acc[am][bn][q] = 0.f;

        auto prefetch = [&](int jt, int buf) {
            const float* src = WhB + (size_t)(jt << 6) * 128;
            float* dstb = smem + SBO(buf);
#pragma unroll
            for (int k = 0; k < 8; k++) {
                int x = ct + (k << 8);
                int r = x >> 5, c4 = (x & 31) << 2;
                cp_async16(saddr(dstb + r * SWS + c4), src + r * 128 + c4);
            }
            asm volatile("cp.async.commit_group;");
        };

        prefetch(0, 0);   // B(0) -> buf0

        for (int jt = 0; jt < 32; jt++) {
            const int buf = jt & 1;
            bar_sync(1 + buf, 512);    // p[buf] full; all consumers past MMA(jt-1)
            if (jt < 31) {
                prefetch(jt + 1, buf ^ 1);
                asm volatile("cp.async.wait_group 1;" ::: "memory");
            } else {
                asm volatile("cp.async.wait_group 0;" ::: "memory");
            }

            const float* P  = smem + SPO(buf);
            const float* Bm = smem + SBO(buf);
            const int rb = wm * 32;
#pragma unroll
            for (int ks = 0; ks < 8; ks++) {
                const int k0 = ks << 3;
                unsigned A0[4], A1[4];
                A0[0] = __float_as_uint(P[(rb + g)      * SPS + k0 + t4]);
                A0[1] = __float_as_uint(P[(rb + g + 8)  * SPS + k0 + t4]);
                A0[2] = __float_as_uint(P[(rb + g)      * SPS + k0 + t4 + 4]);
                A0[3] = __float_as_uint(P[(rb + g + 8)  * SPS + k0 + t4 + 4]);
                A1[0] = __float_as_uint(P[(rb + g + 16) * SPS + k0 + t4]);
                A1[1] = __float_as_uint(P[(rb + g + 24) * SPS + k0 + t4]);
                A1[2] = __float_as_uint(P[(rb + g + 16) * SPS + k0 + t4 + 4]);
                A1[3] = __float_as_uint(P[(rb + g + 24) * SPS + k0 + t4 + 4]);
#pragma unroll
                for (int bn = 0; bn < 8; bn++) {
                    int col = wn * 64 + bn * 8 + g;
                    unsigned b0 = __float_as_uint(Bm[(k0 + t4)     * SWS + col]);
                    unsigned b1 = __float_as_uint(Bm[(k0 + t4 + 4) * SWS + col]);
                    mma_tf32(acc[0][bn], A0, b0, b1);
                    mma_tf32(acc[1][bn], A1, b0, b1);
                }
            }
            bar_arrive(3 + buf, 512);  // p[buf] free
        }

        // epilogue: out = h + h_prime (consumers cover all 128x128)
#pragma unroll
        for (int am = 0; am < 2; am++)
#pragma unroll
            for (int bn = 0; bn < 8; bn++) {
                int row = i0 + wm * 32 + am * 16 + g;
                int col = wn * 64 + bn * 8 + t4 * 2;
                size_t base  = (size_t)(bat * NN + row) * 128 + col;
                size_t base2 = base + 8 * 128;
                outO[base]      = h[base]      + acc[am][bn][0];
                outO[base + 1]  = h[base + 1]  + acc[am][bn][1];
                outO[base2]     = h[base2]     + acc[am][bn][2];
                outO[base2 + 1] = h[base2 + 1] + acc[am][bn][3];
            }
    }
}

// ---------------- host launch ----------------------------------------------
extern "C" void kernel_launch(void* const* d_in, const int* in_sizes, int n_in,
                              void* d_out, int out_size) {
    const float* h   = (const float*)d_in[0];
    const int*   adj = (const int*)d_in[1];
    const float* W   = (const float*)d_in[2];
    const float* a   = (const float*)d_in[3];
    float* outO = (float*)d_out;
    float* outA = outO + (size_t)BB * NN * DD;

    k1_wh<<<NROWS / 64, 256>>>(h, W, a);
    k3_denom<<<dim3(NN / 8, BB), 256>>>(adj);

    cudaFuncSetAttribute(k4_fused, cudaFuncAttributeMaxDynamicSharedMemorySize,
                         K4_SMEM_B);
    k4_fused<<<BB * (NN / 128), 512, K4_SMEM_B>>>(h, outO, outA);
}